// round 15
// baseline (speedup 1.0000x reference)
#include <cuda_runtime.h>
#include <cuda_fp16.h>
#include <cuda.h>
#include <cstdint>

#define Dm 2048
#define Bm 256

// scratch (no cudaMalloc allowed)
__device__ __align__(16) __half g_w2h[Dm * Dm];      // w2 fp16 [2048, 2048]
__device__ __align__(16) __half g_xh[Bm * Dm];       // x  fp16 [256, 2048]
__device__ __align__(16) __half g_yh[Bm * Dm];       // y  fp16 [256, 2048]
__device__ __align__(16) float  g_p[2 * Bm * Dm];    // GEMM2 split-K partials

__device__ __forceinline__ uint32_t pack_h2(float lo, float hi) {
    uint32_t r;
    asm("cvt.rn.f16x2.f32 %0, %1, %2;" : "=r"(r) : "f"(hi), "f"(lo));
    return r;
}
__device__ __forceinline__ void mma16(float* d, const uint32_t* a, const uint32_t* b) {
    asm volatile(
        "mma.sync.aligned.m16n8k16.row.col.f32.f16.f16.f32 "
        "{%0,%1,%2,%3}, {%4,%5,%6,%7}, {%8,%9}, {%0,%1,%2,%3};"
        : "+f"(d[0]), "+f"(d[1]), "+f"(d[2]), "+f"(d[3])
        : "r"(a[0]), "r"(a[1]), "r"(a[2]), "r"(a[3]), "r"(b[0]), "r"(b[1]));
}
__device__ __forceinline__ void ldsm4(uint32_t* r, uint32_t addr) {
    asm volatile("ldmatrix.sync.aligned.m8n8.x4.shared.b16 {%0,%1,%2,%3}, [%4];"
                 : "=r"(r[0]), "=r"(r[1]), "=r"(r[2]), "=r"(r[3]) : "r"(addr));
}
__device__ __forceinline__ float2 lds64(uint32_t addr) {
    float2 v;
    asm volatile("ld.shared.v2.f32 {%0,%1}, [%2];"
                 : "=f"(v.x), "=f"(v.y) : "r"(addr));
    return v;
}
__device__ __forceinline__ void mbar_init(uint32_t addr, uint32_t cnt) {
    asm volatile("mbarrier.init.shared.b64 [%0], %1;" :: "r"(addr), "r"(cnt) : "memory");
}
__device__ __forceinline__ void mbar_expect_tx(uint32_t addr, uint32_t bytes) {
    asm volatile("mbarrier.arrive.expect_tx.shared.b64 _, [%0], %1;"
                 :: "r"(addr), "r"(bytes) : "memory");
}
__device__ __forceinline__ void mbar_wait(uint32_t addr, uint32_t parity) {
    asm volatile(
        "{\n\t.reg .pred P1;\n\t"
        "WL%=:\n\t"
        "mbarrier.try_wait.parity.shared.b64 P1, [%0], %1;\n\t"
        "@P1 bra.uni WD%=;\n\t"
        "bra.uni WL%=;\n\t"
        "WD%=:\n\t}"
        :: "r"(addr), "r"(parity) : "memory");
}
__device__ __forceinline__ void tma2d(uint32_t saddr, const void* tm,
                                      int32_t x, int32_t y, uint32_t mbar) {
    asm volatile(
        "cp.async.bulk.tensor.2d.shared::cta.global.tile.mbarrier::complete_tx::bytes "
        "[%0], [%1, {%2, %3}], [%4];"
        :: "r"(saddr), "l"(tm), "r"(x), "r"(y), "r"(mbar) : "memory");
}

// ---------------------------------------------------------------------------
// fp32 -> fp16 convert for w2 | x only (w1 consumed as fp32 by GEMM1)
// ---------------------------------------------------------------------------
__global__ __launch_bounds__(256) void k_cvt(
    const float4* __restrict__ w2, const float4* __restrict__ x,
    uint2* __restrict__ w2h, uint2* __restrict__ xh)
{
    constexpr int N2 = Dm * Dm / 4;
    constexpr int N3 = Bm * Dm / 4;
    const int stride = gridDim.x * 256;
    for (int i = blockIdx.x * 256 + threadIdx.x; i < N2 + N3; i += stride) {
        const float4* s; uint2* d; int j;
        if (i < N2) { s = w2; d = w2h; j = i; }
        else        { s = x;  d = xh;  j = i - N2; }
        float4 v = s[j];
        d[j] = make_uint2(pack_h2(v.x, v.y), pack_h2(v.z, v.w));
    }
}

// ---------------------------------------------------------------------------
// Fused GEMM1 + gating/conv: each CTA owns a 32-wide d-block and ALL 3 gates
// (BN = 96 = 3 x 32; B rows = w1[gate*2048 + dBase .. +31]).  Warp tile 32x96
// (MT=2, NT=12) so acc[.][j], acc[.][4+j], acc[.][8+j] = Bg, Cg, xg at the
// SAME (b,d).  Epilogue: Bx = Bg*xg, cache roll/scatter, depthwise conv,
// y = Cg*conv -> g_yh (fp16); state -> out_state.  No bcx, no k_elem.
// A: fp16 SW128, ldmatrix.  B: w1 bytes as u16 view, lds64 + pack (as R14).
// ---------------------------------------------------------------------------
__global__ __launch_bounds__(128, 1) void k_g1f(
    const __grid_constant__ CUtensorMap tmA,   // xh  fp16 [2048 x 256]
    const __grid_constant__ CUtensorMap tmB,   // w1 bytes as u16 [4096 x 6144]
    const float* __restrict__ conv_cache,      // [B, D, 4]
    const float* __restrict__ conv_w,          // [D, 4]
    const int*   __restrict__ pos_ids,
    float* __restrict__ out_state,             // [B, D, 4]
    __half* __restrict__ yh)                   // [B, D]
{
    constexpr int STAGES = 4;
    constexpr int ABYT = 128 * 128;             // A stage: 128 rows x 128B
    constexpr int BBYT = 96 * 128;              // one 32-float k-half of B
    constexpr int STGB = ABYT + 2 * BBYT;       // 40960
    constexpr int NSTG = Dm / 64;               // 32

    extern __shared__ uint8_t smem[];
    const int tid = threadIdx.x;
    const int wid = tid >> 5, lane = tid & 31;
    const int g = lane >> 2, c = lane & 3;
    const int wm = wid * 32;                    // 4 warps x 32 rows = 128
    const int mBase = blockIdx.y * 128, dBase = blockIdx.x * 32;

    uint32_t sraw = (uint32_t)__cvta_generic_to_shared(smem);
    const uint32_t mb0 = sraw;
    uint32_t sb0 = (sraw + 1023u) & ~1023u;
    const uint32_t sbA = (sb0 < sraw + 8u * STAGES) ? sb0 + 1024u : sb0;

    if (tid == 0)
        for (int i = 0; i < STAGES; i++) mbar_init(mb0 + i * 8, 1);
    __syncthreads();

    const int lr = lane & 7, mat = lane >> 3;
    const uint32_t axor = (uint32_t)lr << 4;
    const uint32_t acb = (uint32_t)(mat >> 1) * 16;
    uint32_t arow[2];
    #pragma unroll
    for (int mt = 0; mt < 2; mt++)
        arow[mt] = (uint32_t)(wm + mt * 16 + (mat & 1) * 8 + lr) * 128;
    const uint32_t bxor = (uint32_t)g << 4;     // B-frag rows have row%8 == g
    const uint32_t brow0 = (uint32_t)g * 128;   // wn = 0 (warp spans all 96)

    float acc[2][12][4] = {};

    auto issue = [&](int slot, int k0) {        // k0 in floats
        if (tid == 0) {
            const uint32_t bar = mb0 + slot * 8;
            mbar_expect_tx(bar, STGB);
            const uint32_t sb = sbA + slot * STGB;
            tma2d(sb, &tmA, k0, mBase, bar);    // A (fp16 halves coord = k0)
            #pragma unroll
            for (int kh = 0; kh < 2; kh++)
                #pragma unroll
                for (int gt = 0; gt < 3; gt++)
                    tma2d(sb + ABYT + kh * BBYT + gt * 4096, &tmB,
                          2 * k0 + kh * 64, gt * 2048 + dBase, bar);
        }
    };

    #pragma unroll
    for (int s = 0; s < STAGES - 1; s++) issue(s, s * 64);

    int slot = 0, ph = 0, islot = STAGES - 1;
    for (int s = 0; s < NSTG; s++) {
        mbar_wait(mb0 + slot * 8, ph);
        __syncthreads();

        if (s + STAGES - 1 < NSTG) issue(islot, (s + STAGES - 1) * 64);
        islot = (islot + 1 == STAGES) ? 0 : islot + 1;

        const uint32_t sb = sbA + slot * STGB;
        #pragma unroll
        for (int step = 0; step < 4; step++) {
            const uint32_t kb = step * 32;               // A: 16 halves = 32B
            uint32_t af[2][4], bf[12][2];
            #pragma unroll
            for (int mt = 0; mt < 2; mt++)
                ldsm4(af[mt], sb + arow[mt] + ((acb + kb) ^ axor));

            const uint32_t bpart = sb + ABYT + (step >> 1) * BBYT;
            const uint32_t fb = (step & 1) * 64;         // byte base in 128B row
            #pragma unroll
            for (int nt = 0; nt < 12; nt++) {
                const uint32_t ba = bpart + brow0 + nt * 1024;   // 8 rows*128B
                float2 v0 = lds64(ba + ((fb + 8 * c) ^ bxor));
                float2 v1 = lds64(ba + ((fb + 8 * c + 32) ^ bxor));
                bf[nt][0] = pack_h2(v0.x, v0.y);
                bf[nt][1] = pack_h2(v1.x, v1.y);
            }
            #pragma unroll
            for (int mt = 0; mt < 2; mt++)
                #pragma unroll
                for (int nt = 0; nt < 12; nt++)
                    mma16(acc[mt][nt], af[mt], bf[nt]);
        }
        slot++; if (slot == STAGES) { slot = 0; ph ^= 1; }
    }

    // fused epilogue: gates + cache roll/scatter + conv + C-gate
    int pos = pos_ids[0];
    pos = min(max(pos, 0), 3);

    #pragma unroll
    for (int mt = 0; mt < 2; mt++) {
        #pragma unroll
        for (int j = 0; j < 4; j++) {
            const float* aB = acc[mt][j];
            const float* aC = acc[mt][4 + j];
            const float* aX = acc[mt][8 + j];
            const int d0 = dBase + j * 8 + 2 * c;
            #pragma unroll
            for (int rp = 0; rp < 2; rp++) {    // row pair: g, g+8
                const int b = mBase + wm + mt * 16 + g + rp * 8;
                __half yv[2];
                #pragma unroll
                for (int dd = 0; dd < 2; dd++) {
                    const int h = rp * 2 + dd;
                    const size_t idx = (size_t)b * Dm + d0 + dd;
                    const float Bx = aB[h] * aX[h];
                    const float4 cc = *reinterpret_cast<const float4*>(
                        conv_cache + idx * 4);
                    float st[4] = {cc.y, cc.z, cc.w, cc.x};
                    st[pos] = Bx;
                    const float4 cw = *reinterpret_cast<const float4*>(
                        conv_w + (size_t)(d0 + dd) * 4);
                    const float co = st[0] * cw.x + st[1] * cw.y
                                   + st[2] * cw.z + st[3] * cw.w;
                    yv[dd] = __float2half(aC[h] * co);
                    *reinterpret_cast<float4*>(out_state + idx * 4) =
                        make_float4(st[0], st[1], st[2], st[3]);
                }
                *reinterpret_cast<__half2*>(&yh[(size_t)b * Dm + d0]) =
                    *reinterpret_cast<__half2*>(yv);
            }
        }
    }
}

// ---------------------------------------------------------------------------
// GEMM2 (fp16 TMA, 8 warps): p[z] = y @ w2^T over K-half z. Tile 64x128,
// warp 32x32 (grid 2x4), 4 stages, split-K=2.   (unchanged from R14)
// ---------------------------------------------------------------------------
__global__ __launch_bounds__(256, 1) void k_g2(
    const __grid_constant__ CUtensorMap tmA,   // yh  fp16 [2048 x 256]
    const __grid_constant__ CUtensorMap tmB,   // w2h fp16 [2048 x 2048]
    float* __restrict__ C)                     // g_p, ldc = 2048
{
    constexpr int BM = 64, BN = 128, STAGES = 4;
    constexpr int STGB = (BM + BN) * 128;       // 24576
    constexpr int NSTG = (Dm / 2) / 64;         // 16

    extern __shared__ uint8_t smem[];
    const int tid = threadIdx.x;
    const int wid = tid >> 5, lane = tid & 31;
    const int g = lane >> 2, c = lane & 3;
    const int wm = (wid >> 2) * 32, wn = (wid & 3) * 32;
    const int mBase = blockIdx.y * BM, nBase = blockIdx.x * BN;
    const int kBase = blockIdx.z * (Dm / 2);

    uint32_t sraw = (uint32_t)__cvta_generic_to_shared(smem);
    const uint32_t mb0 = sraw;
    uint32_t sb0 = (sraw + 1023u) & ~1023u;
    const uint32_t sbA = (sb0 < sraw + 8u * STAGES) ? sb0 + 1024u : sb0;

    if (tid == 0)
        for (int i = 0; i < STAGES; i++) mbar_init(mb0 + i * 8, 1);
    __syncthreads();

    const int lr = lane & 7, mat = lane >> 3;
    const uint32_t axor = (uint32_t)lr << 4;
    const uint32_t acb = (uint32_t)(mat >> 1) * 16;
    uint32_t arow[2];
    #pragma unroll
    for (int mt = 0; mt < 2; mt++)
        arow[mt] = (uint32_t)(wm + mt * 16 + (mat & 1) * 8 + lr) * 128;
    const uint32_t bcb = (uint32_t)(mat & 1) * 16;
    uint32_t brow[2];
    #pragma unroll
    for (int p = 0; p < 2; p++)
        brow[p] = (uint32_t)(BM + wn + p * 16 + (mat >> 1) * 8 + lr) * 128;

    float acc[2][4][4] = {};

    auto issue = [&](int slot, int k0) {
        if (tid == 0) {
            const uint32_t bar = mb0 + slot * 8;
            mbar_expect_tx(bar, STGB);
            tma2d(sbA + slot * STGB, &tmA, k0, mBase, bar);
            tma2d(sbA + slot * STGB + BM * 128, &tmB, k0, nBase, bar);
        }
    };

    #pragma unroll
    for (int s = 0; s < STAGES - 1; s++) issue(s, kBase + s * 64);

    int slot = 0, ph = 0, islot = STAGES - 1;
    for (int s = 0; s < NSTG; s++) {
        mbar_wait(mb0 + slot * 8, ph);
        __syncthreads();

        if (s + STAGES - 1 < NSTG) issue(islot, kBase + (s + STAGES - 1) * 64);
        islot = (islot + 1 == STAGES) ? 0 : islot + 1;

        const uint32_t sb = sbA + slot * STGB;
        #pragma unroll
        for (int step = 0; step < 4; step++) {
            const uint32_t kb = step * 32;
            uint32_t af[2][4], bf[4][2];
            #pragma unroll
            for (int mt = 0; mt < 2; mt++)
                ldsm4(af[mt], sb + arow[mt] + ((acb + kb) ^ axor));
            #pragma unroll
            for (int p = 0; p < 2; p++) {
                uint32_t r[4];
                ldsm4(r, sb + brow[p] + ((bcb + kb) ^ axor));
                bf[2 * p][0] = r[0]; bf[2 * p][1] = r[1];
                bf[2 * p + 1][0] = r[2]; bf[2 * p + 1][1] = r[3];
            }
            #pragma unroll
            for (int mt = 0; mt < 2; mt++)
                #pragma unroll
                for (int nt = 0; nt < 4; nt++)
                    mma16(acc[mt][nt], af[mt], bf[nt]);
        }
        slot++; if (slot == STAGES) { slot = 0; ph ^= 1; }
    }

    const int rOff = (int)blockIdx.z * Bm;
    #pragma unroll
    for (int mt = 0; mt < 2; mt++) {
        const int row = rOff + mBase + wm + mt * 16 + g;
        #pragma unroll
        for (int nt = 0; nt < 4; nt++) {
            const int col = nBase + wn + nt * 8 + 2 * c;
            *reinterpret_cast<float2*>(&C[(size_t)row * Dm + col]) =
                make_float2(acc[mt][nt][0], acc[mt][nt][1]);
            *reinterpret_cast<float2*>(&C[(size_t)(row + 8) * Dm + col]) =
                make_float2(acc[mt][nt][2], acc[mt][nt][3]);
        }
    }
}

// split-K reduce: out = p0 + p1
__global__ __launch_bounds__(256) void k_red(float* __restrict__ out)
{
    const int i = blockIdx.x * 256 + threadIdx.x;
    const float4 a = reinterpret_cast<const float4*>(g_p)[i];
    const float4 b = reinterpret_cast<const float4*>(g_p + Bm * Dm)[i];
    reinterpret_cast<float4*>(out)[i] =
        make_float4(a.x + b.x, a.y + b.y, a.z + b.z, a.w + b.w);
}

// ---------------------------------------------------------------------------
typedef CUresult (*encode_t)(
    CUtensorMap*, CUtensorMapDataType, cuuint32_t, void*,
    const cuuint64_t*, const cuuint64_t*, const cuuint32_t*, const cuuint32_t*,
    CUtensorMapInterleave, CUtensorMapSwizzle, CUtensorMapL2promotion,
    CUtensorMapFloatOOBfill);

static void make_tm(encode_t enc, CUtensorMap* tm, const void* ptr,
                    uint64_t inner, uint64_t outer,
                    uint32_t box_inner, uint32_t box_outer) {
    cuuint64_t dims[2]    = {inner, outer};
    cuuint64_t strides[1] = {inner * 2};   // uint16 elements everywhere
    cuuint32_t box[2]     = {box_inner, box_outer};
    cuuint32_t es[2]      = {1, 1};
    enc(tm, CU_TENSOR_MAP_DATA_TYPE_UINT16, 2, (void*)ptr, dims, strides, box,
        es, CU_TENSOR_MAP_INTERLEAVE_NONE, CU_TENSOR_MAP_SWIZZLE_128B,
        CU_TENSOR_MAP_L2_PROMOTION_L2_128B, CU_TENSOR_MAP_FLOAT_OOB_FILL_NONE);
}

extern "C" void kernel_launch(void* const* d_in, const int* in_sizes, int n_in,
                              void* d_out, int out_size) {
    const float* x          = (const float*)d_in[0];
    const float* conv_cache = (const float*)d_in[1];
    const float* w1         = (const float*)d_in[2];
    const float* w2         = (const float*)d_in[3];
    const float* conv_w     = (const float*)d_in[4];
    const int*   pos_ids    = (const int*)d_in[5];

    float* out       = (float*)d_out;            // [B,1,D]
    float* out_state = out + (size_t)Bm * Dm;    // [B,D,K]

    float* pp = nullptr;
    __half *w2h = nullptr, *xh = nullptr, *yh = nullptr;
    cudaGetSymbolAddress((void**)&pp, g_p);
    cudaGetSymbolAddress((void**)&w2h, g_w2h);
    cudaGetSymbolAddress((void**)&xh, g_xh);
    cudaGetSymbolAddress((void**)&yh, g_yh);

    void* fp = nullptr;
    cudaDriverEntryPointQueryResult qr;
    cudaGetDriverEntryPoint("cuTensorMapEncodeTiled", &fp, cudaEnableDefault, &qr);
    encode_t enc = (encode_t)fp;

    // All tensor maps use UINT16 element type (byte view; TMA is type-agnostic).
    CUtensorMap tmX, tmW1, tmY, tmW2;
    make_tm(enc, &tmX,  xh,  Dm,     Bm,     64, 128);  // fp16 x
    make_tm(enc, &tmW1, w1,  2 * Dm, 3 * Dm, 64, 32);   // fp32 w1 as u16 bytes
    make_tm(enc, &tmY,  yh,  Dm,     Bm,     64, 64);   // fp16 y
    make_tm(enc, &tmW2, w2h, Dm,     Dm,     64, 128);  // fp16 w2

    // converts (w2 + x only)
    k_cvt<<<1024, 256>>>((const float4*)w2, (const float4*)x,
                         (uint2*)w2h, (uint2*)xh);

    constexpr int SMEM1 = 2048 + 4 * 40960;   // 165888
    constexpr int SMEM2 = 2048 + 4 * 24576;   // 100352
    cudaFuncSetAttribute((const void*)k_g1f,
                         cudaFuncAttributeMaxDynamicSharedMemorySize, SMEM1);
    cudaFuncSetAttribute((const void*)k_g2,
                         cudaFuncAttributeMaxDynamicSharedMemorySize, SMEM2);

    // fused GEMM1 + gating/conv: grid 64 x 2 = 128 CTAs
    k_g1f<<<dim3(Dm / 32, Bm / 128), 128, SMEM1>>>(
        tmX, tmW1, conv_cache, conv_w, pos_ids, out_state, yh);

    // GEMM2 partials (split-K=2); grid 16x4x2 = 128 CTAs
    k_g2<<<dim3(Dm / 128, Bm / 64, 2), 256, SMEM2>>>(tmY, tmW2, pp);

    // out = p0 + p1
    k_red<<<(Bm * Dm / 4) / 256, 256>>>(out);
}

// round 16
// speedup vs baseline: 1.1370x; 1.1370x over previous
#include <cuda_runtime.h>
#include <cuda_fp16.h>
#include <cuda.h>
#include <cstdint>

#define Dm 2048
#define Bm 256

// scratch (no cudaMalloc allowed)
__device__ float g_bcx[Bm * 3 * Dm];                 // GEMM1 out [256, 6144] fp32
__device__ __align__(16) __half g_w2h[Dm * Dm];      // w2 fp16 [2048, 2048]
__device__ __align__(16) __half g_xh[Bm * Dm];       // x  fp16 [256, 2048]
__device__ __align__(16) __half g_yh[Bm * Dm];       // y  fp16 [256, 2048]

__device__ __forceinline__ uint32_t pack_h2(float lo, float hi) {
    uint32_t r;
    asm("cvt.rn.f16x2.f32 %0, %1, %2;" : "=r"(r) : "f"(hi), "f"(lo));
    return r;
}
__device__ __forceinline__ void mma16(float* d, const uint32_t* a, const uint32_t* b) {
    asm volatile(
        "mma.sync.aligned.m16n8k16.row.col.f32.f16.f16.f32 "
        "{%0,%1,%2,%3}, {%4,%5,%6,%7}, {%8,%9}, {%0,%1,%2,%3};"
        : "+f"(d[0]), "+f"(d[1]), "+f"(d[2]), "+f"(d[3])
        : "r"(a[0]), "r"(a[1]), "r"(a[2]), "r"(a[3]), "r"(b[0]), "r"(b[1]));
}
__device__ __forceinline__ void ldsm4(uint32_t* r, uint32_t addr) {
    asm volatile("ldmatrix.sync.aligned.m8n8.x4.shared.b16 {%0,%1,%2,%3}, [%4];"
                 : "=r"(r[0]), "=r"(r[1]), "=r"(r[2]), "=r"(r[3]) : "r"(addr));
}
__device__ __forceinline__ float2 lds64(uint32_t addr) {
    float2 v;
    asm volatile("ld.shared.v2.f32 {%0,%1}, [%2];"
                 : "=f"(v.x), "=f"(v.y) : "r"(addr));
    return v;
}
__device__ __forceinline__ void redg_add(float* p, float v) {
    asm volatile("red.global.add.f32 [%0], %1;" :: "l"(p), "f"(v) : "memory");
}
__device__ __forceinline__ void mbar_init(uint32_t addr, uint32_t cnt) {
    asm volatile("mbarrier.init.shared.b64 [%0], %1;" :: "r"(addr), "r"(cnt) : "memory");
}
__device__ __forceinline__ void mbar_expect_tx(uint32_t addr, uint32_t bytes) {
    asm volatile("mbarrier.arrive.expect_tx.shared.b64 _, [%0], %1;"
                 :: "r"(addr), "r"(bytes) : "memory");
}
__device__ __forceinline__ void mbar_wait(uint32_t addr, uint32_t parity) {
    asm volatile(
        "{\n\t.reg .pred P1;\n\t"
        "WL%=:\n\t"
        "mbarrier.try_wait.parity.shared.b64 P1, [%0], %1;\n\t"
        "@P1 bra.uni WD%=;\n\t"
        "bra.uni WL%=;\n\t"
        "WD%=:\n\t}"
        :: "r"(addr), "r"(parity) : "memory");
}
__device__ __forceinline__ void tma2d(uint32_t saddr, const void* tm,
                                      int32_t x, int32_t y, uint32_t mbar) {
    asm volatile(
        "cp.async.bulk.tensor.2d.shared::cta.global.tile.mbarrier::complete_tx::bytes "
        "[%0], [%1, {%2, %3}], [%4];"
        :: "r"(saddr), "l"(tm), "r"(x), "r"(y), "r"(mbar) : "memory");
}

// ---------------------------------------------------------------------------
// fp32 -> fp16 convert for w2 | x, plus zero-init of `out` (for GEMM2 REDG)
// ---------------------------------------------------------------------------
__global__ __launch_bounds__(256) void k_cvt(
    const float4* __restrict__ w2, const float4* __restrict__ x,
    uint2* __restrict__ w2h, uint2* __restrict__ xh,
    float4* __restrict__ out)
{
    constexpr int N2 = Dm * Dm / 4;
    constexpr int N3 = Bm * Dm / 4;
    const int stride = gridDim.x * 256;
    for (int i = blockIdx.x * 256 + threadIdx.x; i < N2 + 2 * N3; i += stride) {
        if (i < N2) {
            float4 v = w2[i];
            w2h[i] = make_uint2(pack_h2(v.x, v.y), pack_h2(v.z, v.w));
        } else if (i < N2 + N3) {
            float4 v = x[i - N2];
            xh[i - N2] = make_uint2(pack_h2(v.x, v.y), pack_h2(v.z, v.w));
        } else {
            out[i - N2 - N3] = make_float4(0.f, 0.f, 0.f, 0.f);
        }
    }
}

// ---------------------------------------------------------------------------
// GEMM1: BCx[256,6144] = x[256,2048](fp16) @ w1[6144,2048](fp32 bytes)^T
// Tile 128x48, 4 warps of 64x24 (MT4, NT3), BK=64, 3-stage TMA pipeline,
// 2 CTAs/SM (88 KB smem), grid 128 x 2 = 256 CTAs.
// A: fp16 SW128, ldmatrix.  B: w1 bytes as u16 view, lds64 + pack.
// ---------------------------------------------------------------------------
__global__ __launch_bounds__(128, 1) void k_g1(
    const __grid_constant__ CUtensorMap tmA,   // xh  fp16 [2048 x 256]
    const __grid_constant__ CUtensorMap tmB,   // w1 bytes as u16 [4096 x 6144]
    float* __restrict__ C)                     // ldc = 6144
{
    constexpr int STAGES = 3;
    constexpr int ABYT = 128 * 128;             // A stage: 128 rows x 128B
    constexpr int BBYT = 48 * 128;              // one 32-float k-half of B
    constexpr int STGB = ABYT + 2 * BBYT;       // 28672
    constexpr int NSTG = Dm / 64;               // 32

    extern __shared__ uint8_t smem[];
    const int tid = threadIdx.x;
    const int wid = tid >> 5, lane = tid & 31;
    const int g = lane >> 2, c = lane & 3;
    const int wm = (wid >> 1) * 64, wn = (wid & 1) * 24;
    const int mBase = blockIdx.y * 128, nBase = blockIdx.x * 48;

    uint32_t sraw = (uint32_t)__cvta_generic_to_shared(smem);
    const uint32_t mb0 = sraw;
    uint32_t sb0 = (sraw + 1023u) & ~1023u;
    const uint32_t sbA = (sb0 < sraw + 8u * STAGES) ? sb0 + 1024u : sb0;

    if (tid == 0)
        for (int i = 0; i < STAGES; i++) mbar_init(mb0 + i * 8, 1);
    __syncthreads();

    const int lr = lane & 7, mat = lane >> 3;
    const uint32_t axor = (uint32_t)lr << 4;
    const uint32_t acb = (uint32_t)(mat >> 1) * 16;
    uint32_t arow[4];
    #pragma unroll
    for (int mt = 0; mt < 4; mt++)
        arow[mt] = (uint32_t)(wm + mt * 16 + (mat & 1) * 8 + lr) * 128;
    const uint32_t bxor = (uint32_t)g << 4;     // B-frag rows: row%8 == g
    const uint32_t brow0 = (uint32_t)(wn + g) * 128;

    float acc[4][3][4] = {};

    auto issue = [&](int slot, int k0) {        // k0 in floats
        if (tid == 0) {
            const uint32_t bar = mb0 + slot * 8;
            mbar_expect_tx(bar, STGB);
            const uint32_t sb = sbA + slot * STGB;
            tma2d(sb, &tmA, k0, mBase, bar);
            tma2d(sb + ABYT,        &tmB, 2 * k0,      nBase, bar);
            tma2d(sb + ABYT + BBYT, &tmB, 2 * k0 + 64, nBase, bar);
        }
    };

    #pragma unroll
    for (int s = 0; s < STAGES - 1; s++) issue(s, s * 64);

    int slot = 0, ph = 0, islot = STAGES - 1;
    for (int s = 0; s < NSTG; s++) {
        mbar_wait(mb0 + slot * 8, ph);
        __syncthreads();

        if (s + STAGES - 1 < NSTG) issue(islot, (s + STAGES - 1) * 64);
        islot = (islot + 1 == STAGES) ? 0 : islot + 1;

        const uint32_t sb = sbA + slot * STGB;
        #pragma unroll
        for (int step = 0; step < 4; step++) {
            const uint32_t kb = step * 32;               // A: 16 halves = 32B
            uint32_t af[4][4], bf[3][2];
            #pragma unroll
            for (int mt = 0; mt < 4; mt++)
                ldsm4(af[mt], sb + arow[mt] + ((acb + kb) ^ axor));

            const uint32_t bpart = sb + ABYT + (step >> 1) * BBYT;
            const uint32_t fb = (step & 1) * 64;         // byte base in 128B row
            #pragma unroll
            for (int nt = 0; nt < 3; nt++) {
                const uint32_t ba = bpart + brow0 + nt * 1024;   // 8 rows*128B
                float2 v0 = lds64(ba + ((fb + 8 * c) ^ bxor));
                float2 v1 = lds64(ba + ((fb + 8 * c + 32) ^ bxor));
                bf[nt][0] = pack_h2(v0.x, v0.y);
                bf[nt][1] = pack_h2(v1.x, v1.y);
            }
            #pragma unroll
            for (int mt = 0; mt < 4; mt++)
                #pragma unroll
                for (int nt = 0; nt < 3; nt++)
                    mma16(acc[mt][nt], af[mt], bf[nt]);
        }
        slot++; if (slot == STAGES) { slot = 0; ph ^= 1; }
    }

    #pragma unroll
    for (int mt = 0; mt < 4; mt++) {
        const int row = mBase + wm + mt * 16 + g;
        #pragma unroll
        for (int nt = 0; nt < 3; nt++) {
            const int col = nBase + wn + nt * 8 + 2 * c;
            *reinterpret_cast<float2*>(&C[(size_t)row * 6144 + col]) =
                make_float2(acc[mt][nt][0], acc[mt][nt][1]);
            *reinterpret_cast<float2*>(&C[(size_t)(row + 8) * 6144 + col]) =
                make_float2(acc[mt][nt][2], acc[mt][nt][3]);
        }
    }
}

// ---------------------------------------------------------------------------
// GEMM2 (fp16 TMA, 8 warps): out += y @ w2^T over K-half z (split-K=2).
// Tile 64x128, warp 32x32 (grid 2x4), 4 stages. Epilogue: REDG into
// pre-zeroed out (2 contributions per address -> deterministic).
// ---------------------------------------------------------------------------
__global__ __launch_bounds__(256, 1) void k_g2(
    const __grid_constant__ CUtensorMap tmA,   // yh  fp16 [2048 x 256]
    const __grid_constant__ CUtensorMap tmB,   // w2h fp16 [2048 x 2048]
    float* __restrict__ C)                     // out, ldc = 2048
{
    constexpr int BM = 64, BN = 128, STAGES = 4;
    constexpr int STGB = (BM + BN) * 128;       // 24576
    constexpr int NSTG = (Dm / 2) / 64;         // 16

    extern __shared__ uint8_t smem[];
    const int tid = threadIdx.x;
    const int wid = tid >> 5, lane = tid & 31;
    const int g = lane >> 2, c = lane & 3;
    const int wm = (wid >> 2) * 32, wn = (wid & 3) * 32;
    const int mBase = blockIdx.y * BM, nBase = blockIdx.x * BN;
    const int kBase = blockIdx.z * (Dm / 2);

    uint32_t sraw = (uint32_t)__cvta_generic_to_shared(smem);
    const uint32_t mb0 = sraw;
    uint32_t sb0 = (sraw + 1023u) & ~1023u;
    const uint32_t sbA = (sb0 < sraw + 8u * STAGES) ? sb0 + 1024u : sb0;

    if (tid == 0)
        for (int i = 0; i < STAGES; i++) mbar_init(mb0 + i * 8, 1);
    __syncthreads();

    const int lr = lane & 7, mat = lane >> 3;
    const uint32_t axor = (uint32_t)lr << 4;
    const uint32_t acb = (uint32_t)(mat >> 1) * 16;
    uint32_t arow[2];
    #pragma unroll
    for (int mt = 0; mt < 2; mt++)
        arow[mt] = (uint32_t)(wm + mt * 16 + (mat & 1) * 8 + lr) * 128;
    const uint32_t bcb = (uint32_t)(mat & 1) * 16;
    uint32_t brow[2];
    #pragma unroll
    for (int p = 0; p < 2; p++)
        brow[p] = (uint32_t)(BM + wn + p * 16 + (mat >> 1) * 8 + lr) * 128;

    float acc[2][4][4] = {};

    auto issue = [&](int slot, int k0) {
        if (tid == 0) {
            const uint32_t bar = mb0 + slot * 8;
            mbar_expect_tx(bar, STGB);
            tma2d(sbA + slot * STGB, &tmA, k0, mBase, bar);
            tma2d(sbA + slot * STGB + BM * 128, &tmB, k0, nBase, bar);
        }
    };

    #pragma unroll
    for (int s = 0; s < STAGES - 1; s++) issue(s, kBase + s * 64);

    int slot = 0, ph = 0, islot = STAGES - 1;
    for (int s = 0; s < NSTG; s++) {
        mbar_wait(mb0 + slot * 8, ph);
        __syncthreads();

        if (s + STAGES - 1 < NSTG) issue(islot, kBase + (s + STAGES - 1) * 64);
        islot = (islot + 1 == STAGES) ? 0 : islot + 1;

        const uint32_t sb = sbA + slot * STGB;
        #pragma unroll
        for (int step = 0; step < 4; step++) {
            const uint32_t kb = step * 32;
            uint32_t af[2][4], bf[4][2];
            #pragma unroll
            for (int mt = 0; mt < 2; mt++)
                ldsm4(af[mt], sb + arow[mt] + ((acb + kb) ^ axor));
            #pragma unroll
            for (int p = 0; p < 2; p++) {
                uint32_t r[4];
                ldsm4(r, sb + brow[p] + ((bcb + kb) ^ axor));
                bf[2 * p][0] = r[0]; bf[2 * p][1] = r[1];
                bf[2 * p + 1][0] = r[2]; bf[2 * p + 1][1] = r[3];
            }
            #pragma unroll
            for (int mt = 0; mt < 2; mt++)
                #pragma unroll
                for (int nt = 0; nt < 4; nt++)
                    mma16(acc[mt][nt], af[mt], bf[nt]);
        }
        slot++; if (slot == STAGES) { slot = 0; ph ^= 1; }
    }

    // REDG epilogue into pre-zeroed out
    #pragma unroll
    for (int mt = 0; mt < 2; mt++) {
        const int row = mBase + wm + mt * 16 + g;
        #pragma unroll
        for (int nt = 0; nt < 4; nt++) {
            const int col = nBase + wn + nt * 8 + 2 * c;
            redg_add(&C[(size_t)row * Dm + col],           acc[mt][nt][0]);
            redg_add(&C[(size_t)row * Dm + col + 1],       acc[mt][nt][1]);
            redg_add(&C[(size_t)(row + 8) * Dm + col],     acc[mt][nt][2]);
            redg_add(&C[(size_t)(row + 8) * Dm + col + 1], acc[mt][nt][3]);
        }
    }
}

// ---------------------------------------------------------------------------
// Elementwise: gates + cache roll/scatter + depthwise conv + C-gate -> y fp16
// ---------------------------------------------------------------------------
__global__ __launch_bounds__(256) void k_elem(
    const float* __restrict__ conv_cache, const float* __restrict__ conv_w,
    const int* __restrict__ pos_ids, float* __restrict__ out_state)
{
    const int idx = blockIdx.x * 256 + threadIdx.x;   // b*2048 + d
    const int b = idx >> 11, d = idx & 2047;

    const float Bg = g_bcx[(size_t)b * 6144 + d];
    const float Cg = g_bcx[(size_t)b * 6144 + 2048 + d];
    const float xg = g_bcx[(size_t)b * 6144 + 4096 + d];
    const float Bx = Bg * xg;

    int pos = pos_ids[0];
    pos = min(max(pos, 0), 3);

    const float4 cc = *reinterpret_cast<const float4*>(conv_cache + (size_t)idx * 4);
    float st[4] = {cc.y, cc.z, cc.w, cc.x};
    st[pos] = Bx;

    const float4 cw = *reinterpret_cast<const float4*>(conv_w + (size_t)d * 4);
    const float co = st[0] * cw.x + st[1] * cw.y + st[2] * cw.z + st[3] * cw.w;

    g_yh[idx] = __float2half(Cg * co);
    *reinterpret_cast<float4*>(out_state + (size_t)idx * 4) =
        make_float4(st[0], st[1], st[2], st[3]);
}

// ---------------------------------------------------------------------------
typedef CUresult (*encode_t)(
    CUtensorMap*, CUtensorMapDataType, cuuint32_t, void*,
    const cuuint64_t*, const cuuint64_t*, const cuuint32_t*, const cuuint32_t*,
    CUtensorMapInterleave, CUtensorMapSwizzle, CUtensorMapL2promotion,
    CUtensorMapFloatOOBfill);

static void make_tm(encode_t enc, CUtensorMap* tm, const void* ptr,
                    uint64_t inner, uint64_t outer,
                    uint32_t box_inner, uint32_t box_outer) {
    cuuint64_t dims[2]    = {inner, outer};
    cuuint64_t strides[1] = {inner * 2};   // uint16 elements everywhere
    cuuint32_t box[2]     = {box_inner, box_outer};
    cuuint32_t es[2]      = {1, 1};
    enc(tm, CU_TENSOR_MAP_DATA_TYPE_UINT16, 2, (void*)ptr, dims, strides, box,
        es, CU_TENSOR_MAP_INTERLEAVE_NONE, CU_TENSOR_MAP_SWIZZLE_128B,
        CU_TENSOR_MAP_L2_PROMOTION_L2_128B, CU_TENSOR_MAP_FLOAT_OOB_FILL_NONE);
}

extern "C" void kernel_launch(void* const* d_in, const int* in_sizes, int n_in,
                              void* d_out, int out_size) {
    const float* x          = (const float*)d_in[0];
    const float* conv_cache = (const float*)d_in[1];
    const float* w1         = (const float*)d_in[2];
    const float* w2         = (const float*)d_in[3];
    const float* conv_w     = (const float*)d_in[4];
    const int*   pos_ids    = (const int*)d_in[5];

    float* out       = (float*)d_out;            // [B,1,D]
    float* out_state = out + (size_t)Bm * Dm;    // [B,D,K]

    float* bcx = nullptr;
    __half *w2h = nullptr, *xh = nullptr, *yh = nullptr;
    cudaGetSymbolAddress((void**)&bcx, g_bcx);
    cudaGetSymbolAddress((void**)&w2h, g_w2h);
    cudaGetSymbolAddress((void**)&xh, g_xh);
    cudaGetSymbolAddress((void**)&yh, g_yh);

    void* fp = nullptr;
    cudaDriverEntryPointQueryResult qr;
    cudaGetDriverEntryPoint("cuTensorMapEncodeTiled", &fp, cudaEnableDefault, &qr);
    encode_t enc = (encode_t)fp;

    // All tensor maps use UINT16 element type (byte view; TMA is type-agnostic).
    CUtensorMap tmX, tmW1, tmY, tmW2;
    make_tm(enc, &tmX,  xh,  Dm,     Bm,     64, 128);  // fp16 x
    make_tm(enc, &tmW1, w1,  2 * Dm, 3 * Dm, 64, 48);   // fp32 w1 as u16 bytes
    make_tm(enc, &tmY,  yh,  Dm,     Bm,     64, 64);   // fp16 y
    make_tm(enc, &tmW2, w2h, Dm,     Dm,     64, 128);  // fp16 w2

    // converts (w2 + x) + zero-init out for REDG
    k_cvt<<<1024, 256>>>((const float4*)w2, (const float4*)x,
                         (uint2*)w2h, (uint2*)xh, (float4*)out);

    constexpr int SMEM1 = 2048 + 3 * 28672;   // 88064 -> 2 CTAs/SM
    constexpr int SMEM2 = 2048 + 4 * 24576;   // 100352
    cudaFuncSetAttribute((const void*)k_g1,
                         cudaFuncAttributeMaxDynamicSharedMemorySize, SMEM1);
    cudaFuncSetAttribute((const void*)k_g2,
                         cudaFuncAttributeMaxDynamicSharedMemorySize, SMEM2);

    // GEMM1: BCx = x @ w1^T (w1 fp32 on the fly); grid 128 x 2 = 256 CTAs
    k_g1<<<dim3(3 * Dm / 48, Bm / 128), 128, SMEM1>>>(tmX, tmW1, bcx);

    // gating + conv + state scatter
    k_elem<<<(Bm * Dm) / 256, 256>>>(conv_cache, conv_w, pos_ids, out_state);

    // GEMM2: out += y @ w2^T (split-K=2, REDG); grid 16x4x2 = 128 CTAs
    k_g2<<<dim3(Dm / 128, Bm / 64, 2), 256, SMEM2>>>(tmY, tmW2, out);
}